// round 11
// baseline (speedup 1.0000x reference)
#include <cuda_runtime.h>
#include <cuda_bf16.h>
#include <cstdint>

// Problem constants: B=16, H=16, M=256, N=576, D=1024
#define BB 16
#define HH 16
#define MM 256
#define NN 576
#define DD 1024

#define EPSF 1e-8f
#define MU_C (1.0f / 576.0f)
#define FI_C (1.0f / 1.1f)

// ---------------- device scratch ----------------
__device__ __nv_bfloat16 g_xb[BB * NN * DD];   // visual feats bf16 (raw)
__device__ __nv_bfloat16 g_yb[BB * MM * DD];   // text feats bf16 (raw)
__device__ float g_inv_nx[BB * NN];
__device__ float g_inv_ny[BB * MM];
__device__ float g_K[BB * MM * NN];            // K, then overwritten with P*mask
__device__ float g_LS[BB * MM * NN];           // sum_h log(student)
__device__ float g_vpart[2][8][BB * NN];       // per-rank partial Ktu (parity buffered)
__device__ float g_partial[BB * MM];
__device__ unsigned g_done;

// ---------------- helpers ----------------
__device__ __forceinline__ float warp_sum(float v) {
#pragma unroll
    for (int o = 16; o; o >>= 1) v += __shfl_xor_sync(0xffffffffu, v, o);
    return v;
}

__device__ __forceinline__ float block_sum512(float v, volatile float* red) {
    int tid = threadIdx.x;
    float w = warp_sum(v);
    if ((tid & 31) == 0) red[tid >> 5] = w;
    __syncthreads();
    if (tid < 32) {
        float r = (tid < 16) ? red[tid] : 0.0f;
        r = warp_sum(r);
        if (tid == 0) red[0] = r;
    }
    __syncthreads();
    float out = red[0];
    __syncthreads();
    return out;
}

__device__ __forceinline__ float block_sum288(float v, volatile float* red) {
    int tid = threadIdx.x;
    float w = warp_sum(v);
    if ((tid & 31) == 0) red[tid >> 5] = w;
    __syncthreads();
    if (tid < 32) {
        float r = (tid < 9) ? red[tid] : 0.0f;
        r = warp_sum(r);
        if (tid == 0) red[0] = r;
    }
    __syncthreads();
    return red[0];
}

__device__ __forceinline__ void cluster_sync() {
    asm volatile("barrier.cluster.arrive.aligned;" ::: "memory");
    asm volatile("barrier.cluster.wait.aligned;" ::: "memory");
}

// cluster-scope fence: orders this CTA's global writes for cluster peers
// (consumed together with the acquire in barrier.cluster.wait). MUCH cheaper
// than __threadfence() (MEMBAR.GPU) which must drain to gpu scope.
__device__ __forceinline__ void fence_cluster() {
    asm volatile("fence.acq_rel.cluster;" ::: "memory");
}

__device__ __forceinline__ void ldsm4(uint32_t* r, uint32_t addr) {
    asm volatile("ldmatrix.sync.aligned.m8n8.x4.shared.b16 {%0,%1,%2,%3}, [%4];"
                 : "=r"(r[0]), "=r"(r[1]), "=r"(r[2]), "=r"(r[3]) : "r"(addr));
}

__device__ __forceinline__ void mma16816(float* c, const uint32_t* a, const uint32_t* b) {
    asm volatile(
        "mma.sync.aligned.m16n8k16.row.col.f32.bf16.bf16.f32 "
        "{%0,%1,%2,%3}, {%4,%5,%6,%7}, {%8,%9}, {%0,%1,%2,%3};"
        : "+f"(c[0]), "+f"(c[1]), "+f"(c[2]), "+f"(c[3])
        : "r"(a[0]), "r"(a[1]), "r"(a[2]), "r"(a[3]), "r"(b[0]), "r"(b[1]));
}

__device__ __forceinline__ void cp16(uint32_t dst, const void* src) {
    asm volatile("cp.async.cg.shared.global [%0], [%1], 16;" :: "r"(dst), "l"(src));
}

// ---------------- kernel 1: norms + bf16 conversion ----------------
__global__ void __launch_bounds__(256) prep_kernel(const float* __restrict__ visual,
                                                   const float* __restrict__ text) {
    int warp = blockIdx.x * 8 + (threadIdx.x >> 5);
    int lane = threadIdx.x & 31;
    const int VROWS = BB * NN;
    const float* src;
    __nv_bfloat16* dst;
    float* invp;
    if (warp < VROWS) {
        src = visual + (size_t)warp * DD;
        dst = g_xb + (size_t)warp * DD;
        invp = g_inv_nx + warp;
    } else {
        int r = warp - VROWS;
        src = text + (size_t)r * DD;
        dst = g_yb + (size_t)r * DD;
        invp = g_inv_ny + r;
    }
    const float4* s4 = (const float4*)src;
    uint2* d2 = (uint2*)dst;
    float ss = 0.0f;
#pragma unroll
    for (int i = 0; i < 8; ++i) {
        float4 v = __ldcs(&s4[lane + 32 * i]);
        ss += v.x * v.x + v.y * v.y + v.z * v.z + v.w * v.w;
        uint32_t lo = (uint32_t)__bfloat16_as_ushort(__float2bfloat16_rn(v.x))
                    | ((uint32_t)__bfloat16_as_ushort(__float2bfloat16_rn(v.y)) << 16);
        uint32_t hi = (uint32_t)__bfloat16_as_ushort(__float2bfloat16_rn(v.z))
                    | ((uint32_t)__bfloat16_as_ushort(__float2bfloat16_rn(v.w)) << 16);
        d2[lane + 32 * i] = make_uint2(lo, hi);
    }
    ss = warp_sum(ss);
    if (lane == 0) *invp = rsqrtf(ss + 1e-12f);
}

// ---------------- kernel 2: HMMA bf16 GEMM, 3-stage cp.async pipeline --------
#define ASTG 16384
#define BSTG 8192
__global__ void __launch_bounds__(256) gemm_expK_kernel() {
    extern __shared__ __align__(16) char dsm[];
    uint32_t SBASE = (uint32_t)__cvta_generic_to_shared(dsm);
    uint32_t SA = SBASE;                 // 3 x 16384
    uint32_t SB = SBASE + 3 * ASTG;      // 3 x 8192

    int tid = threadIdx.x, wid = tid >> 5, lane = tid & 31;
    int nt = blockIdx.x, mt = blockIdx.y, b = blockIdx.z;
    int wm = wid & 3, wn = wid >> 2;

    const __nv_bfloat16* Abase = g_yb + ((size_t)(b * MM + mt * 128)) * DD;
    const __nv_bfloat16* Bbase = g_xb + ((size_t)(b * NN + nt * 64)) * DD;

    float acc[2][4][4];
#pragma unroll
    for (int i = 0; i < 2; ++i)
#pragma unroll
        for (int j = 0; j < 4; ++j)
#pragma unroll
            for (int k = 0; k < 4; ++k) acc[i][j][k] = 0.0f;

    int a_row0 = wm * 32 + ((lane >> 3) & 1) * 8 + (lane & 7);
    int a_chunk_sel = (lane >> 4);
    int b_row0 = wn * 32 + (lane >> 4) * 8 + (lane & 7);
    int b_chunk_sel = ((lane >> 3) & 1);

    int arow[4], acol[4], brow[2], bcol[2];
    uint32_t aoff[4], boff[2];
#pragma unroll
    for (int q = 0; q < 4; ++q) {
        int c = tid + 256 * q;
        arow[q] = c >> 3; acol[q] = c & 7;
        aoff[q] = arow[q] * 128 + ((acol[q] ^ (arow[q] & 7)) * 16);
    }
#pragma unroll
    for (int q = 0; q < 2; ++q) {
        int c = tid + 256 * q;
        brow[q] = c >> 3; bcol[q] = c & 7;
        boff[q] = brow[q] * 128 + ((bcol[q] ^ (brow[q] & 7)) * 16);
    }

#define ISSUE(s)                                                               \
    do {                                                                       \
        int st_ = (s) % 3;                                                     \
        int kb_ = (s) * 64;                                                    \
        uint32_t ab_ = SA + st_ * ASTG, bb_ = SB + st_ * BSTG;                 \
        _Pragma("unroll")                                                      \
        for (int q = 0; q < 4; ++q)                                            \
            cp16(ab_ + aoff[q], Abase + (size_t)arow[q] * DD + kb_ + acol[q] * 8); \
        _Pragma("unroll")                                                      \
        for (int q = 0; q < 2; ++q)                                            \
            cp16(bb_ + boff[q], Bbase + (size_t)brow[q] * DD + kb_ + bcol[q] * 8); \
        asm volatile("cp.async.commit_group;" ::: "memory");                   \
    } while (0)

    ISSUE(0);
    ISSUE(1);

    for (int s = 0; s < 16; ++s) {
        if (s == 15)
            asm volatile("cp.async.wait_group 0;" ::: "memory");
        else
            asm volatile("cp.async.wait_group 1;" ::: "memory");
        __syncthreads();
        if (s + 2 < 16) ISSUE(s + 2);

        uint32_t SAc = SA + (s % 3) * ASTG;
        uint32_t SBc = SB + (s % 3) * BSTG;
#pragma unroll
        for (int kk = 0; kk < 4; ++kk) {
            uint32_t a0[4], a1[4], bA[4], bB[4];
            {
                int row = a_row0;
                int ch = kk * 2 + a_chunk_sel;
                ldsm4(a0, SAc + row * 128 + ((ch ^ (row & 7)) * 16));
                row = a_row0 + 16;
                ldsm4(a1, SAc + row * 128 + ((ch ^ (row & 7)) * 16));
            }
            {
                int row = b_row0;
                int ch = kk * 2 + b_chunk_sel;
                ldsm4(bA, SBc + row * 128 + ((ch ^ (row & 7)) * 16));
                row = b_row0 + 16;
                ldsm4(bB, SBc + row * 128 + ((ch ^ (row & 7)) * 16));
            }
            mma16816(acc[0][0], a0, bA + 0);
            mma16816(acc[0][1], a0, bA + 2);
            mma16816(acc[0][2], a0, bB + 0);
            mma16816(acc[0][3], a0, bB + 2);
            mma16816(acc[1][0], a1, bA + 0);
            mma16816(acc[1][1], a1, bA + 2);
            mma16816(acc[1][2], a1, bB + 0);
            mma16816(acc[1][3], a1, bB + 2);
        }
    }

    // epilogue: scale by inv-norms, exp((cos-1)*10), write g_K
    int mrow_base = mt * 128 + wm * 32 + (lane >> 2);
    int ncol_base = nt * 64 + wn * 32 + (lane & 3) * 2;
    const float* invx = g_inv_nx + b * NN;
    const float* invy = g_inv_ny + b * MM;
#pragma unroll
    for (int mi = 0; mi < 2; ++mi) {
#pragma unroll
        for (int half = 0; half < 2; ++half) {
            int m = mrow_base + mi * 16 + half * 8;
            float invm = invy[m];
            float* out = g_K + ((size_t)(b * MM + m)) * NN;
#pragma unroll
            for (int ni = 0; ni < 4; ++ni) {
                int n = ncol_base + ni * 8;
                float c0 = acc[mi][ni][half * 2 + 0];
                float c1 = acc[mi][ni][half * 2 + 1];
                float s0 = c0 * invm * invx[n];
                float s1 = c1 * invm * invx[n + 1];
                float2 e;
                e.x = __expf((s0 - 1.0f) * 10.0f);
                e.y = __expf((s1 - 1.0f) * 10.0f);
                *(float2*)(out + n) = e;
            }
        }
    }
}

// ---------------- kernel 3: Sinkhorn + teacher finalize (cluster per batch) ----
// grid = 128 CTAs (16 clusters x 8) x 512 threads. K slice in smem; the
// inter-CTA vpart exchange is ordered by fence.acq_rel.cluster + cluster barrier
// (NOT gpu-scope membar -- that was the 7k-cycle/iter stall).
#define KSLICE (32 * NN)
__global__ void __cluster_dims__(8, 1, 1) __launch_bounds__(512)
sinkhorn_kernel(const float* __restrict__ mask) {
    extern __shared__ __align__(16) float sk[];   // [32][NN]
    __shared__ float vsm[NN];
    __shared__ float usm[32];
    __shared__ float masksm[32];
    __shared__ float nusm[32];
    __shared__ float red[16];
    int tid = threadIdx.x;
    int b = blockIdx.x >> 3;
    int rank = blockIdx.x & 7;
    int wid = tid >> 5, lane = tid & 31;
    const int row0 = rank * 32;

    float mv = (tid < MM) ? mask[b * MM + tid] : 0.0f;
    float msum = block_sum512(mv, red);
    if (tid < 32) {
        float mk = mask[b * MM + row0 + tid];
        masksm[tid] = mk;
        nusm[tid] = mk / (msum + EPSF);
    }

    float* Kbase = g_K + ((size_t)(b * MM + row0)) * NN;
    // stage K slice into smem (coalesced float4; 18432 f4 / 512 thr = 36 each)
    {
        const float4* src = (const float4*)Kbase;
        float4* dst = (float4*)sk;
#pragma unroll
        for (int i = 0; i < KSLICE / 4 / 512; ++i)
            dst[tid + 512 * i] = src[tid + 512 * i];
    }
    __syncthreads();

    const int rl0 = wid * 2, rl1 = wid * 2 + 1;
    const float* K0 = sk + rl0 * NN;
    const float* K1 = sk + rl1 * NN;

    for (int it = 0; it < 5; ++it) {
        // ---- build v in smem from previous iteration's partials ----
        if (it == 0) {
            for (int j = tid; j < NN; j += 512) vsm[j] = 1.0f;
        } else {
            const float (*vp)[BB * NN] = g_vpart[(it - 1) & 1];
            for (int j = tid; j < NN; j += 512) {
                float s = 0.0f;
#pragma unroll
                for (int r = 0; r < 8; ++r) s += __ldcg(&vp[r][b * NN + j]);
                vsm[j] = __powf(MU_C / (s + EPSF), FI_C);
            }
        }
        __syncthreads();

        // ---- phase A: u for 2 rows per warp (smem) ----
        {
            float acc0 = 0.0f, acc1 = 0.0f;
#pragma unroll
            for (int i = 0; i < 18; ++i) {
                int j = lane + 32 * i;
                float vv = vsm[j];
                acc0 += K0[j] * vv;
                acc1 += K1[j] * vv;
            }
            acc0 = warp_sum(acc0);
            acc1 = warp_sum(acc1);
            if (lane == 0) {
                usm[rl0] = __powf(nusm[rl0] / (acc0 + EPSF), FI_C);
                usm[rl1] = __powf(nusm[rl1] / (acc1 + EPSF), FI_C);
            }
        }
        __syncthreads();

        // ---- phase B: partial Ktu over own rows (smem), 576 cols / 512 thr ----
        float a0 = 0.0f, a1 = 0.0f;
#pragma unroll 8
        for (int r = 0; r < 32; ++r) {
            const float* Kr = sk + r * NN;
            float ur = usm[r];
            a0 += Kr[tid] * ur;
            if (tid < 64) a1 += Kr[tid + 512] * ur;
        }
        float* vp = g_vpart[it & 1][rank] + b * NN;
        vp[tid] = a0;
        if (tid < 64) vp[tid + 512] = a1;
        fence_cluster();
        cluster_sync();
    }

    // ---- tail: final v, then P finalize (smem -> global) ----
    {
        const float (*vp)[BB * NN] = g_vpart[0];
        for (int j = tid; j < NN; j += 512) {
            float s = 0.0f;
#pragma unroll
            for (int r = 0; r < 8; ++r) s += __ldcg(&vp[r][b * NN + j]);
            vsm[j] = __powf(MU_C / (s + EPSF), FI_C);
        }
    }
    __syncthreads();
#pragma unroll
    for (int r = 0; r < 2; ++r) {
        int rl = wid * 2 + r;
        const float* Kr = sk + rl * NN;
        float* Kg = Kbase + (size_t)rl * NN;
        float u = usm[rl];
        float pj[18];
        float rs = 0.0f;
#pragma unroll
        for (int i = 0; i < 18; ++i) {
            int j = lane + 32 * i;
            float p = u * Kr[j] * vsm[j];
            pj[i] = p;
            rs += p;
        }
        rs = warp_sum(rs);
        float scale = masksm[rl] / (rs + EPSF);
#pragma unroll
        for (int i = 0; i < 18; ++i) {
            int j = lane + 32 * i;
            Kg[j] = pj[i] * scale;
        }
    }
}

// ---------------- logsum: LS[b,m,j] = sum_h log(student + eps) ----------------
// Forked at capture start; overlaps prep + GEMM + Sinkhorn.
__global__ void __launch_bounds__(288) logsum_kernel(const float* __restrict__ student) {
    int blk = blockIdx.x, tid = threadIdx.x;
    int b = blk >> 8, m = blk & 255;
    const float* sbase = student + ((size_t)(b * HH) * MM + m) * NN;
    float2 sv[HH];
#pragma unroll
    for (int h = 0; h < HH; ++h)
        sv[h] = __ldcs((const float2*)(sbase + (size_t)h * MM * NN) + tid);
    float2 r = make_float2(0.0f, 0.0f);
#pragma unroll
    for (int h = 0; h < HH; ++h) {
        r.x += __logf(sv[h].x + EPSF);
        r.y += __logf(sv[h].y + EPSF);
    }
    ((float2*)(g_LS + (size_t)blk * NN))[tid] = r;
}

// ---------------- dot: sum P * LS + fused deterministic final reduce ----------
__global__ void __launch_bounds__(288) dot_kernel(float* __restrict__ out) {
    __shared__ float red[9];
    __shared__ bool last;
    int blk = blockIdx.x, tid = threadIdx.x;
    const float2* P = (const float2*)(g_K + (size_t)blk * NN);
    const float2* L = (const float2*)(g_LS + (size_t)blk * NN);
    float2 p = P[tid], l = L[tid];
    float acc = p.x * l.x + p.y * l.y;
    float tot = block_sum288(acc, red);
    if (tid == 0) {
        g_partial[blk] = tot;
        __threadfence();
        unsigned t = atomicAdd(&g_done, 1u);
        last = (t == (unsigned)(BB * MM - 1));
    }
    __syncthreads();
    if (last) {
        if (tid == 0) g_done = 0;  // reset for next graph replay
        float s = 0.0f;
        for (int i = tid; i < BB * MM; i += 288) s += g_partial[i];
        float t2 = block_sum288(s, red);
        if (tid == 0) out[0] = -t2 * (1.0f / (float)(BB * HH * MM));
    }
}

// ---------------- launch ----------------
extern "C" void kernel_launch(void* const* d_in, const int* in_sizes, int n_in,
                              void* d_out, int out_size) {
    const float *student = nullptr, *visual = nullptr, *text = nullptr, *mask = nullptr;
    for (int i = 0; i < n_in; ++i) {
        long sz = in_sizes[i];
        if (sz == (long)BB * HH * MM * NN) student = (const float*)d_in[i];
        else if (sz == (long)BB * NN * DD) visual = (const float*)d_in[i];
        else if (sz == (long)BB * MM * DD) text = (const float*)d_in[i];
        else if (sz == (long)BB * MM) mask = (const float*)d_in[i];
    }
    float* out = (float*)d_out;

    static cudaStream_t s2;
    static cudaEvent_t evA, evB;
    static bool init_done = false;
    if (!init_done) {
        cudaFuncSetAttribute(gemm_expK_kernel,
                             cudaFuncAttributeMaxDynamicSharedMemorySize,
                             3 * (ASTG + BSTG));
        cudaFuncSetAttribute(sinkhorn_kernel,
                             cudaFuncAttributeMaxDynamicSharedMemorySize,
                             KSLICE * 4);
        cudaStreamCreateWithFlags(&s2, cudaStreamNonBlocking);
        cudaEventCreateWithFlags(&evA, cudaEventDisableTiming);
        cudaEventCreateWithFlags(&evB, cudaEventDisableTiming);
        init_done = true;
    }

    // stream 0: prep -> gemm -> sinkhorn -> dot
    // stream s2: logsum (student only), forked at start, joined before dot
    cudaEventRecord(evA, 0);
    cudaStreamWaitEvent(s2, evA, 0);
    logsum_kernel<<<BB * MM, 288, 0, s2>>>(student);
    prep_kernel<<<(BB * NN + BB * MM) / 8, 256>>>(visual, text);
    gemm_expK_kernel<<<dim3(NN / 64, MM / 128, BB), 256, 3 * (ASTG + BSTG)>>>();
    sinkhorn_kernel<<<128, 512, KSLICE * 4>>>(mask);
    cudaEventRecord(evB, s2);
    cudaStreamWaitEvent(0, evB, 0);
    dot_kernel<<<BB * MM, 288>>>(out);
}

// round 12
// speedup vs baseline: 1.0157x; 1.0157x over previous
#include <cuda_runtime.h>
#include <cuda_bf16.h>
#include <cstdint>

// Problem constants: B=16, H=16, M=256, N=576, D=1024
#define BB 16
#define HH 16
#define MM 256
#define NN 576
#define DD 1024

#define EPSF 1e-8f
#define MU_C (1.0f / 576.0f)
#define FI_C (1.0f / 1.1f)

// ---------------- device scratch ----------------
__device__ __nv_bfloat16 g_xb[BB * NN * DD];   // visual feats bf16 (raw)
__device__ __nv_bfloat16 g_yb[BB * MM * DD];   // text feats bf16 (raw)
__device__ float g_inv_nx[BB * NN];
__device__ float g_inv_ny[BB * MM];
__device__ float g_K[BB * MM * NN];            // K, then overwritten with P*mask
__device__ float g_LS[BB * MM * NN];           // sum_h log(student)
__device__ float g_partial[BB * MM];
__device__ unsigned g_done;

// ---------------- helpers ----------------
__device__ __forceinline__ float warp_sum(float v) {
#pragma unroll
    for (int o = 16; o; o >>= 1) v += __shfl_xor_sync(0xffffffffu, v, o);
    return v;
}

__device__ __forceinline__ float block_sum288(float v, volatile float* red) {
    int tid = threadIdx.x;
    float w = warp_sum(v);
    if ((tid & 31) == 0) red[tid >> 5] = w;
    __syncthreads();
    if (tid < 32) {
        float r = (tid < 9) ? red[tid] : 0.0f;
        r = warp_sum(r);
        if (tid == 0) red[0] = r;
    }
    __syncthreads();
    return red[0];
}

__device__ __forceinline__ float block_sum1024(float v, volatile float* red) {
    int tid = threadIdx.x;
    float w = warp_sum(v);
    if ((tid & 31) == 0) red[tid >> 5] = w;
    __syncthreads();
    if (tid < 32) {
        float r = red[tid];
        r = warp_sum(r);
        if (tid == 0) red[0] = r;
    }
    __syncthreads();
    float out = red[0];
    __syncthreads();
    return out;
}

__device__ __forceinline__ void cluster_sync() {
    asm volatile("barrier.cluster.arrive.aligned;" ::: "memory");
    asm volatile("barrier.cluster.wait.aligned;" ::: "memory");
}

__device__ __forceinline__ uint32_t smem_u32(const void* p) {
    return (uint32_t)__cvta_generic_to_shared(p);
}

// store float into the same smem offset of cluster CTA `rank`
__device__ __forceinline__ void dsmem_store(uint32_t laddr, int rank, float v) {
    uint32_t r;
    asm volatile("mapa.shared::cluster.u32 %0, %1, %2;" : "=r"(r) : "r"(laddr), "r"(rank));
    asm volatile("st.shared::cluster.f32 [%0], %1;" :: "r"(r), "f"(v) : "memory");
}

__device__ __forceinline__ void mbar_arrive_rank(uint32_t laddr, int rank) {
    uint32_t r;
    asm volatile("mapa.shared::cluster.u32 %0, %1, %2;" : "=r"(r) : "r"(laddr), "r"(rank));
    asm volatile("mbarrier.arrive.shared::cluster.b64 _, [%0];" :: "r"(r) : "memory");
}

__device__ __forceinline__ void mbar_wait_parity(uint32_t mb, uint32_t parity) {
    uint32_t done;
    asm volatile(
        "{\n\t.reg .pred p;\n\t"
        "mbarrier.try_wait.parity.acquire.cluster.shared::cta.b64 p, [%1], %2;\n\t"
        "selp.b32 %0,1,0,p;\n\t}"
        : "=r"(done) : "r"(mb), "r"(parity) : "memory");
    while (!done) {
        asm volatile(
            "{\n\t.reg .pred p;\n\t"
            "mbarrier.try_wait.parity.acquire.cluster.shared::cta.b64 p, [%1], %2, 0x989680;\n\t"
            "selp.b32 %0,1,0,p;\n\t}"
            : "=r"(done) : "r"(mb), "r"(parity) : "memory");
    }
}

__device__ __forceinline__ void ldsm4(uint32_t* r, uint32_t addr) {
    asm volatile("ldmatrix.sync.aligned.m8n8.x4.shared.b16 {%0,%1,%2,%3}, [%4];"
                 : "=r"(r[0]), "=r"(r[1]), "=r"(r[2]), "=r"(r[3]) : "r"(addr));
}

__device__ __forceinline__ void mma16816(float* c, const uint32_t* a, const uint32_t* b) {
    asm volatile(
        "mma.sync.aligned.m16n8k16.row.col.f32.bf16.bf16.f32 "
        "{%0,%1,%2,%3}, {%4,%5,%6,%7}, {%8,%9}, {%0,%1,%2,%3};"
        : "+f"(c[0]), "+f"(c[1]), "+f"(c[2]), "+f"(c[3])
        : "r"(a[0]), "r"(a[1]), "r"(a[2]), "r"(a[3]), "r"(b[0]), "r"(b[1]));
}

__device__ __forceinline__ void cp16(uint32_t dst, const void* src) {
    asm volatile("cp.async.cg.shared.global [%0], [%1], 16;" :: "r"(dst), "l"(src));
}

// ---------------- kernel 1: norms + bf16 conversion ----------------
__global__ void __launch_bounds__(256) prep_kernel(const float* __restrict__ visual,
                                                   const float* __restrict__ text) {
    int warp = blockIdx.x * 8 + (threadIdx.x >> 5);
    int lane = threadIdx.x & 31;
    const int VROWS = BB * NN;
    const float* src;
    __nv_bfloat16* dst;
    float* invp;
    if (warp < VROWS) {
        src = visual + (size_t)warp * DD;
        dst = g_xb + (size_t)warp * DD;
        invp = g_inv_nx + warp;
    } else {
        int r = warp - VROWS;
        src = text + (size_t)r * DD;
        dst = g_yb + (size_t)r * DD;
        invp = g_inv_ny + r;
    }
    const float4* s4 = (const float4*)src;
    uint2* d2 = (uint2*)dst;
    float ss = 0.0f;
#pragma unroll
    for (int i = 0; i < 8; ++i) {
        float4 v = __ldcs(&s4[lane + 32 * i]);
        ss += v.x * v.x + v.y * v.y + v.z * v.z + v.w * v.w;
        uint32_t lo = (uint32_t)__bfloat16_as_ushort(__float2bfloat16_rn(v.x))
                    | ((uint32_t)__bfloat16_as_ushort(__float2bfloat16_rn(v.y)) << 16);
        uint32_t hi = (uint32_t)__bfloat16_as_ushort(__float2bfloat16_rn(v.z))
                    | ((uint32_t)__bfloat16_as_ushort(__float2bfloat16_rn(v.w)) << 16);
        d2[lane + 32 * i] = make_uint2(lo, hi);
    }
    ss = warp_sum(ss);
    if (lane == 0) *invp = rsqrtf(ss + 1e-12f);
}

// ---------------- kernel 2: HMMA bf16 GEMM, 3-stage cp.async pipeline --------
#define ASTG 16384
#define BSTG 8192
__global__ void __launch_bounds__(256) gemm_expK_kernel() {
    extern __shared__ __align__(16) char dsm[];
    uint32_t SBASE = (uint32_t)__cvta_generic_to_shared(dsm);
    uint32_t SA = SBASE;                 // 3 x 16384
    uint32_t SB = SBASE + 3 * ASTG;      // 3 x 8192

    int tid = threadIdx.x, wid = tid >> 5, lane = tid & 31;
    int nt = blockIdx.x, mt = blockIdx.y, b = blockIdx.z;
    int wm = wid & 3, wn = wid >> 2;

    const __nv_bfloat16* Abase = g_yb + ((size_t)(b * MM + mt * 128)) * DD;
    const __nv_bfloat16* Bbase = g_xb + ((size_t)(b * NN + nt * 64)) * DD;

    float acc[2][4][4];
#pragma unroll
    for (int i = 0; i < 2; ++i)
#pragma unroll
        for (int j = 0; j < 4; ++j)
#pragma unroll
            for (int k = 0; k < 4; ++k) acc[i][j][k] = 0.0f;

    int a_row0 = wm * 32 + ((lane >> 3) & 1) * 8 + (lane & 7);
    int a_chunk_sel = (lane >> 4);
    int b_row0 = wn * 32 + (lane >> 4) * 8 + (lane & 7);
    int b_chunk_sel = ((lane >> 3) & 1);

    int arow[4], acol[4], brow[2], bcol[2];
    uint32_t aoff[4], boff[2];
#pragma unroll
    for (int q = 0; q < 4; ++q) {
        int c = tid + 256 * q;
        arow[q] = c >> 3; acol[q] = c & 7;
        aoff[q] = arow[q] * 128 + ((acol[q] ^ (arow[q] & 7)) * 16);
    }
#pragma unroll
    for (int q = 0; q < 2; ++q) {
        int c = tid + 256 * q;
        brow[q] = c >> 3; bcol[q] = c & 7;
        boff[q] = brow[q] * 128 + ((bcol[q] ^ (brow[q] & 7)) * 16);
    }

#define ISSUE(s)                                                               \
    do {                                                                       \
        int st_ = (s) % 3;                                                     \
        int kb_ = (s) * 64;                                                    \
        uint32_t ab_ = SA + st_ * ASTG, bb_ = SB + st_ * BSTG;                 \
        _Pragma("unroll")                                                      \
        for (int q = 0; q < 4; ++q)                                            \
            cp16(ab_ + aoff[q], Abase + (size_t)arow[q] * DD + kb_ + acol[q] * 8); \
        _Pragma("unroll")                                                      \
        for (int q = 0; q < 2; ++q)                                            \
            cp16(bb_ + boff[q], Bbase + (size_t)brow[q] * DD + kb_ + bcol[q] * 8); \
        asm volatile("cp.async.commit_group;" ::: "memory");                   \
    } while (0)

    ISSUE(0);
    ISSUE(1);

    for (int s = 0; s < 16; ++s) {
        if (s == 15)
            asm volatile("cp.async.wait_group 0;" ::: "memory");
        else
            asm volatile("cp.async.wait_group 1;" ::: "memory");
        __syncthreads();
        if (s + 2 < 16) ISSUE(s + 2);

        uint32_t SAc = SA + (s % 3) * ASTG;
        uint32_t SBc = SB + (s % 3) * BSTG;
#pragma unroll
        for (int kk = 0; kk < 4; ++kk) {
            uint32_t a0[4], a1[4], bA[4], bB[4];
            {
                int row = a_row0;
                int ch = kk * 2 + a_chunk_sel;
                ldsm4(a0, SAc + row * 128 + ((ch ^ (row & 7)) * 16));
                row = a_row0 + 16;
                ldsm4(a1, SAc + row * 128 + ((ch ^ (row & 7)) * 16));
            }
            {
                int row = b_row0;
                int ch = kk * 2 + b_chunk_sel;
                ldsm4(bA, SBc + row * 128 + ((ch ^ (row & 7)) * 16));
                row = b_row0 + 16;
                ldsm4(bB, SBc + row * 128 + ((ch ^ (row & 7)) * 16));
            }
            mma16816(acc[0][0], a0, bA + 0);
            mma16816(acc[0][1], a0, bA + 2);
            mma16816(acc[0][2], a0, bB + 0);
            mma16816(acc[0][3], a0, bB + 2);
            mma16816(acc[1][0], a1, bA + 0);
            mma16816(acc[1][1], a1, bA + 2);
            mma16816(acc[1][2], a1, bB + 0);
            mma16816(acc[1][3], a1, bB + 2);
        }
    }

    // epilogue: scale by inv-norms, exp((cos-1)*10), write g_K
    int mrow_base = mt * 128 + wm * 32 + (lane >> 2);
    int ncol_base = nt * 64 + wn * 32 + (lane & 3) * 2;
    const float* invx = g_inv_nx + b * NN;
    const float* invy = g_inv_ny + b * MM;
#pragma unroll
    for (int mi = 0; mi < 2; ++mi) {
#pragma unroll
        for (int half = 0; half < 2; ++half) {
            int m = mrow_base + mi * 16 + half * 8;
            float invm = invy[m];
            float* out = g_K + ((size_t)(b * MM + m)) * NN;
#pragma unroll
            for (int ni = 0; ni < 4; ++ni) {
                int n = ncol_base + ni * 8;
                float c0 = acc[mi][ni][half * 2 + 0];
                float c1 = acc[mi][ni][half * 2 + 1];
                float s0 = c0 * invm * invx[n];
                float s1 = c1 * invm * invx[n + 1];
                float2 e;
                e.x = __expf((s0 - 1.0f) * 10.0f);
                e.y = __expf((s1 - 1.0f) * 10.0f);
                *(float2*)(out + n) = e;
            }
        }
    }
}

// ---------------- kernel 3: Sinkhorn, 4-CTA cluster per batch, DSMEM exchange -
// grid = 64 CTAs (16 clusters x 4) x 1024 threads. CTA owns 64 K-rows (144 KB
// smem). Ktu partials are PUSHED into every peer's smem (mapa + st.shared::
// cluster) and signaled with a single per-CTA mbarrier -- no cluster barrier
// and no global-memory exchange inside the loop.
#define KSLICE (64 * NN)
__global__ void __cluster_dims__(4, 1, 1) __launch_bounds__(1024)
sinkhorn_kernel(const float* __restrict__ mask) {
    extern __shared__ __align__(16) float sk[];   // [64][NN]
    __shared__ float vsm[NN];
    __shared__ float usm[64];
    __shared__ float masksm[64];
    __shared__ float nusm[64];
    __shared__ float red[32];
    __shared__ float pbuf[2][512];
    __shared__ float pbuf2[2][64];
    __shared__ float vbuf[2][4][NN];              // parity-buffered partials
    __shared__ __align__(8) unsigned long long mbar;

    int tid = threadIdx.x;
    int b = blockIdx.x >> 2;
    int rank = blockIdx.x & 3;
    int wid = tid >> 5, lane = tid & 31;
    const int row0 = rank * 64;
    uint32_t mb = smem_u32(&mbar);

    if (tid == 0)
        asm volatile("mbarrier.init.shared.b64 [%0], %1;" :: "r"(mb), "r"(4u) : "memory");

    float mv = (tid < MM) ? mask[b * MM + tid] : 0.0f;
    float msum = block_sum1024(mv, red);
    if (tid < 64) {
        float mk = mask[b * MM + row0 + tid];
        masksm[tid] = mk;
        nusm[tid] = mk / (msum + EPSF);
    }

    float* Kbase = g_K + ((size_t)(b * MM + row0)) * NN;
    // stage K slice into smem (9216 float4 / 1024 thr = 9 each)
    {
        const float4* src = (const float4*)Kbase;
        float4* dst = (float4*)sk;
#pragma unroll
        for (int i = 0; i < KSLICE / 4 / 1024; ++i)
            dst[tid + 1024 * i] = src[tid + 1024 * i];
    }
    __syncthreads();
    cluster_sync();   // all mbarriers initialized before any remote arrive

    const int rl0 = wid * 2, rl1 = wid * 2 + 1;
    const float* K0 = sk + rl0 * NN;
    const float* K1 = sk + rl1 * NN;

    for (int it = 0; it < 5; ++it) {
        // ---- build v from previous partials (all reads LOCAL smem) ----
        if (tid < NN) {
            if (it == 0) {
                vsm[tid] = 1.0f;
            } else {
                const float(*vb)[NN] = vbuf[(it - 1) & 1];
                float s = vb[0][tid] + vb[1][tid] + vb[2][tid] + vb[3][tid];
                vsm[tid] = __powf(MU_C / (s + EPSF), FI_C);
            }
        }
        __syncthreads();

        // ---- phase A: u for 2 rows per warp ----
        {
            float acc0 = 0.0f, acc1 = 0.0f;
#pragma unroll
            for (int i = 0; i < 18; ++i) {
                int j = lane + 32 * i;
                float vv = vsm[j];
                acc0 += K0[j] * vv;
                acc1 += K1[j] * vv;
            }
            acc0 = warp_sum(acc0);
            acc1 = warp_sum(acc1);
            if (lane == 0) {
                usm[rl0] = __powf(nusm[rl0] / (acc0 + EPSF), FI_C);
                usm[rl1] = __powf(nusm[rl1] / (acc1 + EPSF), FI_C);
            }
        }
        __syncthreads();

        // ---- phase B: partial Ktu over 64 rows, split in row halves ----
        {
            int half = tid >> 9;          // 0 or 1
            int ct = tid & 511;
            const float* base = sk + half * 32 * NN;
            const float* uh = usm + half * 32;
            float a0 = 0.0f, a1 = 0.0f;
#pragma unroll 8
            for (int r = 0; r < 32; ++r) {
                float ur = uh[r];
                a0 += base[r * NN + ct] * ur;
                if (ct < 64) a1 += base[r * NN + 512 + ct] * ur;
            }
            pbuf[half][ct] = a0;
            if (ct < 64) pbuf2[half][ct] = a1;
        }
        __syncthreads();

        // ---- distribute combined partial to all 4 CTAs' vbuf[it&1][rank] ----
        if (tid < NN) {
            float val = (tid < 512) ? (pbuf[0][tid] + pbuf[1][tid])
                                    : (pbuf2[0][tid - 512] + pbuf2[1][tid - 512]);
            uint32_t laddr = smem_u32(&vbuf[it & 1][rank][tid]);
            vbuf[it & 1][rank][tid] = val;   // local copy
#pragma unroll
            for (int p = 0; p < 4; ++p)
                if (p != rank) dsmem_store(laddr, p, val);
        }
        __syncthreads();
        if (tid == 0) {
            asm volatile("fence.acq_rel.cluster;" ::: "memory");
#pragma unroll
            for (int p = 0; p < 4; ++p) mbar_arrive_rank(mb, p);
        }
        mbar_wait_parity(mb, (uint32_t)(it & 1));
    }

    // ---- tail: final v (phase B of it=4 -> buffer 0), then P finalize ----
    if (tid < NN) {
        const float(*vb)[NN] = vbuf[0];
        float s = vb[0][tid] + vb[1][tid] + vb[2][tid] + vb[3][tid];
        vsm[tid] = __powf(MU_C / (s + EPSF), FI_C);
    }
    __syncthreads();
#pragma unroll
    for (int r = 0; r < 2; ++r) {
        int rl = wid * 2 + r;
        const float* Kr = sk + rl * NN;
        float* Kg = Kbase + (size_t)rl * NN;
        float u = usm[rl];
        float pj[18];
        float rs = 0.0f;
#pragma unroll
        for (int i = 0; i < 18; ++i) {
            int j = lane + 32 * i;
            float p = u * Kr[j] * vsm[j];
            pj[i] = p;
            rs += p;
        }
        rs = warp_sum(rs);
        float scale = masksm[rl] / (rs + EPSF);
#pragma unroll
        for (int i = 0; i < 18; ++i) {
            int j = lane + 32 * i;
            Kg[j] = pj[i] * scale;
        }
    }
    cluster_sync();   // teardown safety
}

// ---------------- logsum: LS[b,m,j] = sum_h log(student + eps) ----------------
// Forked at capture start; overlaps prep + GEMM + Sinkhorn.
__global__ void __launch_bounds__(288) logsum_kernel(const float* __restrict__ student) {
    int blk = blockIdx.x, tid = threadIdx.x;
    int b = blk >> 8, m = blk & 255;
    const float* sbase = student + ((size_t)(b * HH) * MM + m) * NN;
    float2 sv[HH];
#pragma unroll
    for (int h = 0; h < HH; ++h)
        sv[h] = __ldcs((const float2*)(sbase + (size_t)h * MM * NN) + tid);
    float2 r = make_float2(0.0f, 0.0f);
#pragma unroll
    for (int h = 0; h < HH; ++h) {
        r.x += __logf(sv[h].x + EPSF);
        r.y += __logf(sv[h].y + EPSF);
    }
    ((float2*)(g_LS + (size_t)blk * NN))[tid] = r;
}

// ---------------- dot: sum P * LS + fused deterministic final reduce ----------
__global__ void __launch_bounds__(288) dot_kernel(float* __restrict__ out) {
    __shared__ float red[9];
    __shared__ bool last;
    int blk = blockIdx.x, tid = threadIdx.x;
    const float2* P = (const float2*)(g_K + (size_t)blk * NN);
    const float2* L = (const float2*)(g_LS + (size_t)blk * NN);
    float2 p = P[tid], l = L[tid];
    float acc = p.x * l.x + p.y * l.y;
    float tot = block_sum288(acc, red);
    if (tid == 0) {
        g_partial[blk] = tot;
        __threadfence();
        unsigned t = atomicAdd(&g_done, 1u);
        last = (t == (unsigned)(BB * MM - 1));
    }
    __syncthreads();
    if (last) {
        if (tid == 0) g_done = 0;  // reset for next graph replay
        float s = 0.0f;
        for (int i = tid; i < BB * MM; i += 288) s += g_partial[i];
        float t2 = block_sum288(s, red);
        if (tid == 0) out[0] = -t2 * (1.0f / (float)(BB * HH * MM));
    }
}

// ---------------- launch ----------------
extern "C" void kernel_launch(void* const* d_in, const int* in_sizes, int n_in,
                              void* d_out, int out_size) {
    const float *student = nullptr, *visual = nullptr, *text = nullptr, *mask = nullptr;
    for (int i = 0; i < n_in; ++i) {
        long sz = in_sizes[i];
        if (sz == (long)BB * HH * MM * NN) student = (const float*)d_in[i];
        else if (sz == (long)BB * NN * DD) visual = (const float*)d_in[i];
        else if (sz == (long)BB * MM * DD) text = (const float*)d_in[i];
        else if (sz == (long)BB * MM) mask = (const float*)d_in[i];
    }
    float* out = (float*)d_out;

    static cudaStream_t s2;
    static cudaEvent_t evA, evB;
    static bool init_done = false;
    if (!init_done) {
        cudaFuncSetAttribute(gemm_expK_kernel,
                             cudaFuncAttributeMaxDynamicSharedMemorySize,
                             3 * (ASTG + BSTG));
        cudaFuncSetAttribute(sinkhorn_kernel,
                             cudaFuncAttributeMaxDynamicSharedMemorySize,
                             KSLICE * 4);
        cudaStreamCreateWithFlags(&s2, cudaStreamNonBlocking);
        cudaEventCreateWithFlags(&evA, cudaEventDisableTiming);
        cudaEventCreateWithFlags(&evB, cudaEventDisableTiming);
        init_done = true;
    }

    // stream 0: prep -> gemm -> sinkhorn -> dot
    // stream s2: logsum (student only), forked at start, joined before dot
    cudaEventRecord(evA, 0);
    cudaStreamWaitEvent(s2, evA, 0);
    logsum_kernel<<<BB * MM, 288, 0, s2>>>(student);
    prep_kernel<<<(BB * NN + BB * MM) / 8, 256>>>(visual, text);
    gemm_expK_kernel<<<dim3(NN / 64, MM / 128, BB), 256, 3 * (ASTG + BSTG)>>>();
    sinkhorn_kernel<<<64, 1024, KSLICE * 4>>>(mask);
    cudaEventRecord(evB, s2);
    cudaStreamWaitEvent(0, evB, 0);
    dot_kernel<<<BB * MM, 288>>>(out);
}

// round 15
// speedup vs baseline: 1.1226x; 1.1053x over previous
#include <cuda_runtime.h>
#include <cuda_bf16.h>
#include <cstdint>

// Problem constants: B=16, H=16, M=256, N=576, D=1024
#define BB 16
#define HH 16
#define MM 256
#define NN 576
#define DD 1024

#define EPSF 1e-8f
#define MU_C (1.0f / 576.0f)
#define FI_C (1.0f / 1.1f)

// ---------------- device scratch ----------------
__device__ __nv_bfloat16 g_xb[BB * NN * DD];   // visual feats bf16 (raw)
__device__ __nv_bfloat16 g_yb[BB * MM * DD];   // text feats bf16 (raw)
__device__ float g_inv_nx[BB * NN];
__device__ float g_inv_ny[BB * MM];
__device__ float g_K[BB * MM * NN];            // exp(-cost/eps)
__device__ float g_LS[BB * MM * NN];           // sum_h log(student)
__device__ float g_psum[64];                   // per-sinkhorn-CTA loss partials
__device__ unsigned g_done;

// ---------------- helpers ----------------
__device__ __forceinline__ float warp_sum(float v) {
#pragma unroll
    for (int o = 16; o; o >>= 1) v += __shfl_xor_sync(0xffffffffu, v, o);
    return v;
}

__device__ __forceinline__ float block_sum1024(float v, volatile float* red) {
    int tid = threadIdx.x;
    float w = warp_sum(v);
    if ((tid & 31) == 0) red[tid >> 5] = w;
    __syncthreads();
    if (tid < 32) {
        float r = red[tid];
        r = warp_sum(r);
        if (tid == 0) red[0] = r;
    }
    __syncthreads();
    float out = red[0];
    __syncthreads();
    return out;
}

__device__ __forceinline__ void cluster_sync() {
    asm volatile("barrier.cluster.arrive.aligned;" ::: "memory");
    asm volatile("barrier.cluster.wait.aligned;" ::: "memory");
}

__device__ __forceinline__ uint32_t smem_u32(const void* p) {
    return (uint32_t)__cvta_generic_to_shared(p);
}

__device__ __forceinline__ void dsmem_store(uint32_t laddr, int rank, float v) {
    uint32_t r;
    asm volatile("mapa.shared::cluster.u32 %0, %1, %2;" : "=r"(r) : "r"(laddr), "r"(rank));
    asm volatile("st.shared::cluster.f32 [%0], %1;" :: "r"(r), "f"(v) : "memory");
}

__device__ __forceinline__ void mbar_arrive_rank(uint32_t laddr, int rank) {
    uint32_t r;
    asm volatile("mapa.shared::cluster.u32 %0, %1, %2;" : "=r"(r) : "r"(laddr), "r"(rank));
    asm volatile("mbarrier.arrive.shared::cluster.b64 _, [%0];" :: "r"(r) : "memory");
}

__device__ __forceinline__ void mbar_wait_parity(uint32_t mb, uint32_t parity) {
    uint32_t done;
    asm volatile(
        "{\n\t.reg .pred p;\n\t"
        "mbarrier.try_wait.parity.acquire.cluster.shared::cta.b64 p, [%1], %2;\n\t"
        "selp.b32 %0,1,0,p;\n\t}"
        : "=r"(done) : "r"(mb), "r"(parity) : "memory");
    while (!done) {
        asm volatile(
            "{\n\t.reg .pred p;\n\t"
            "mbarrier.try_wait.parity.acquire.cluster.shared::cta.b64 p, [%1], %2, 0x989680;\n\t"
            "selp.b32 %0,1,0,p;\n\t}"
            : "=r"(done) : "r"(mb), "r"(parity) : "memory");
    }
}

__device__ __forceinline__ void ldsm4(uint32_t* r, uint32_t addr) {
    asm volatile("ldmatrix.sync.aligned.m8n8.x4.shared.b16 {%0,%1,%2,%3}, [%4];"
                 : "=r"(r[0]), "=r"(r[1]), "=r"(r[2]), "=r"(r[3]) : "r"(addr));
}

__device__ __forceinline__ void mma16816(float* c, const uint32_t* a, const uint32_t* b) {
    asm volatile(
        "mma.sync.aligned.m16n8k16.row.col.f32.bf16.bf16.f32 "
        "{%0,%1,%2,%3}, {%4,%5,%6,%7}, {%8,%9}, {%0,%1,%2,%3};"
        : "+f"(c[0]), "+f"(c[1]), "+f"(c[2]), "+f"(c[3])
        : "r"(a[0]), "r"(a[1]), "r"(a[2]), "r"(a[3]), "r"(b[0]), "r"(b[1]));
}

__device__ __forceinline__ void cp16(uint32_t dst, const void* src) {
    asm volatile("cp.async.cg.shared.global [%0], [%1], 16;" :: "r"(dst), "l"(src));
}

// ---------------- kernel 1: norms + bf16 conversion ----------------
__global__ void __launch_bounds__(256) prep_kernel(const float* __restrict__ visual,
                                                   const float* __restrict__ text) {
    int warp = blockIdx.x * 8 + (threadIdx.x >> 5);
    int lane = threadIdx.x & 31;
    const int VROWS = BB * NN;
    const float* src;
    __nv_bfloat16* dst;
    float* invp;
    if (warp < VROWS) {
        src = visual + (size_t)warp * DD;
        dst = g_xb + (size_t)warp * DD;
        invp = g_inv_nx + warp;
    } else {
        int r = warp - VROWS;
        src = text + (size_t)r * DD;
        dst = g_yb + (size_t)r * DD;
        invp = g_inv_ny + r;
    }
    const float4* s4 = (const float4*)src;
    uint2* d2 = (uint2*)dst;
    float ss = 0.0f;
#pragma unroll
    for (int i = 0; i < 8; ++i) {
        float4 v = __ldcs(&s4[lane + 32 * i]);
        ss += v.x * v.x + v.y * v.y + v.z * v.z + v.w * v.w;
        uint32_t lo = (uint32_t)__bfloat16_as_ushort(__float2bfloat16_rn(v.x))
                    | ((uint32_t)__bfloat16_as_ushort(__float2bfloat16_rn(v.y)) << 16);
        uint32_t hi = (uint32_t)__bfloat16_as_ushort(__float2bfloat16_rn(v.z))
                    | ((uint32_t)__bfloat16_as_ushort(__float2bfloat16_rn(v.w)) << 16);
        d2[lane + 32 * i] = make_uint2(lo, hi);
    }
    ss = warp_sum(ss);
    if (lane == 0) *invp = rsqrtf(ss + 1e-12f);
}

// ---------------- kernel 2: HMMA bf16 GEMM, 3-stage cp.async pipeline --------
#define ASTG 16384
#define BSTG 8192
__global__ void __launch_bounds__(256) gemm_expK_kernel() {
    extern __shared__ __align__(16) char dsm[];
    uint32_t SBASE = (uint32_t)__cvta_generic_to_shared(dsm);
    uint32_t SA = SBASE;                 // 3 x 16384
    uint32_t SB = SBASE + 3 * ASTG;      // 3 x 8192

    int tid = threadIdx.x, wid = tid >> 5, lane = tid & 31;
    int nt = blockIdx.x, mt = blockIdx.y, b = blockIdx.z;
    int wm = wid & 3, wn = wid >> 2;

    const __nv_bfloat16* Abase = g_yb + ((size_t)(b * MM + mt * 128)) * DD;
    const __nv_bfloat16* Bbase = g_xb + ((size_t)(b * NN + nt * 64)) * DD;

    float acc[2][4][4];
#pragma unroll
    for (int i = 0; i < 2; ++i)
#pragma unroll
        for (int j = 0; j < 4; ++j)
#pragma unroll
            for (int k = 0; k < 4; ++k) acc[i][j][k] = 0.0f;

    int a_row0 = wm * 32 + ((lane >> 3) & 1) * 8 + (lane & 7);
    int a_chunk_sel = (lane >> 4);
    int b_row0 = wn * 32 + (lane >> 4) * 8 + (lane & 7);
    int b_chunk_sel = ((lane >> 3) & 1);

    int arow[4], acol[4], brow[2], bcol[2];
    uint32_t aoff[4], boff[2];
#pragma unroll
    for (int q = 0; q < 4; ++q) {
        int c = tid + 256 * q;
        arow[q] = c >> 3; acol[q] = c & 7;
        aoff[q] = arow[q] * 128 + ((acol[q] ^ (arow[q] & 7)) * 16);
    }
#pragma unroll
    for (int q = 0; q < 2; ++q) {
        int c = tid + 256 * q;
        brow[q] = c >> 3; bcol[q] = c & 7;
        boff[q] = brow[q] * 128 + ((bcol[q] ^ (brow[q] & 7)) * 16);
    }

#define ISSUE(s)                                                               \
    do {                                                                       \
        int st_ = (s) % 3;                                                     \
        int kb_ = (s) * 64;                                                    \
        uint32_t ab_ = SA + st_ * ASTG, bb_ = SB + st_ * BSTG;                 \
        _Pragma("unroll")                                                      \
        for (int q = 0; q < 4; ++q)                                            \
            cp16(ab_ + aoff[q], Abase + (size_t)arow[q] * DD + kb_ + acol[q] * 8); \
        _Pragma("unroll")                                                      \
        for (int q = 0; q < 2; ++q)                                            \
            cp16(bb_ + boff[q], Bbase + (size_t)brow[q] * DD + kb_ + bcol[q] * 8); \
        asm volatile("cp.async.commit_group;" ::: "memory");                   \
    } while (0)

    ISSUE(0);
    ISSUE(1);

    for (int s = 0; s < 16; ++s) {
        if (s == 15)
            asm volatile("cp.async.wait_group 0;" ::: "memory");
        else
            asm volatile("cp.async.wait_group 1;" ::: "memory");
        __syncthreads();
        if (s + 2 < 16) ISSUE(s + 2);

        uint32_t SAc = SA + (s % 3) * ASTG;
        uint32_t SBc = SB + (s % 3) * BSTG;
#pragma unroll
        for (int kk = 0; kk < 4; ++kk) {
            uint32_t a0[4], a1[4], bA[4], bB[4];
            {
                int row = a_row0;
                int ch = kk * 2 + a_chunk_sel;
                ldsm4(a0, SAc + row * 128 + ((ch ^ (row & 7)) * 16));
                row = a_row0 + 16;
                ldsm4(a1, SAc + row * 128 + ((ch ^ (row & 7)) * 16));
            }
            {
                int row = b_row0;
                int ch = kk * 2 + b_chunk_sel;
                ldsm4(bA, SBc + row * 128 + ((ch ^ (row & 7)) * 16));
                row = b_row0 + 16;
                ldsm4(bB, SBc + row * 128 + ((ch ^ (row & 7)) * 16));
            }
            mma16816(acc[0][0], a0, bA + 0);
            mma16816(acc[0][1], a0, bA + 2);
            mma16816(acc[0][2], a0, bB + 0);
            mma16816(acc[0][3], a0, bB + 2);
            mma16816(acc[1][0], a1, bA + 0);
            mma16816(acc[1][1], a1, bA + 2);
            mma16816(acc[1][2], a1, bB + 0);
            mma16816(acc[1][3], a1, bB + 2);
        }
    }

    // epilogue: scale by inv-norms, exp((cos-1)*10), write g_K
    int mrow_base = mt * 128 + wm * 32 + (lane >> 2);
    int ncol_base = nt * 64 + wn * 32 + (lane & 3) * 2;
    const float* invx = g_inv_nx + b * NN;
    const float* invy = g_inv_ny + b * MM;
#pragma unroll
    for (int mi = 0; mi < 2; ++mi) {
#pragma unroll
        for (int half = 0; half < 2; ++half) {
            int m = mrow_base + mi * 16 + half * 8;
            float invm = invy[m];
            float* out = g_K + ((size_t)(b * MM + m)) * NN;
#pragma unroll
            for (int ni = 0; ni < 4; ++ni) {
                int n = ncol_base + ni * 8;
                float c0 = acc[mi][ni][half * 2 + 0];
                float c1 = acc[mi][ni][half * 2 + 1];
                float s0 = c0 * invm * invx[n];
                float s1 = c1 * invm * invx[n + 1];
                float2 e;
                e.x = __expf((s0 - 1.0f) * 10.0f);
                e.y = __expf((s1 - 1.0f) * 10.0f);
                *(float2*)(out + n) = e;
            }
        }
    }
}

// ---------------- kernel 3: Sinkhorn + FUSED loss tail --------------------
// grid = 64 CTAs (16 clusters x 4) x 1024 threads. CTA owns 64 K-rows (144 KB
// smem). DSMEM push exchange per iteration. Tail computes
// sum_rows mask*(P_hat . LS) directly (P never written back); the last CTA
// (deterministic counter) does the fixed-order final reduction into out.
#define KSLICE (64 * NN)
__global__ void __cluster_dims__(4, 1, 1) __launch_bounds__(1024)
sinkhorn_kernel(const float* __restrict__ mask, float* __restrict__ out) {
    extern __shared__ __align__(16) float sk[];   // [64][NN]
    __shared__ float vsm[NN];
    __shared__ float usm[64];
    __shared__ float masksm[64];
    __shared__ float nusm[64];
    __shared__ float red[32];
    __shared__ float pbuf[2][512];
    __shared__ float pbuf2[2][64];
    __shared__ float vbuf[2][4][NN];              // parity-buffered partials
    __shared__ __align__(8) unsigned long long mbar;
    __shared__ bool last;

    int tid = threadIdx.x;
    int b = blockIdx.x >> 2;
    int rank = blockIdx.x & 3;
    int wid = tid >> 5, lane = tid & 31;
    const int row0 = rank * 64;
    uint32_t mb = smem_u32(&mbar);

    if (tid == 0)
        asm volatile("mbarrier.init.shared.b64 [%0], %1;" :: "r"(mb), "r"(4u) : "memory");

    float mv = (tid < MM) ? mask[b * MM + tid] : 0.0f;
    float msum = block_sum1024(mv, red);
    if (tid < 64) {
        float mk = mask[b * MM + row0 + tid];
        masksm[tid] = mk;
        nusm[tid] = mk / (msum + EPSF);
    }

    float* Kbase = g_K + ((size_t)(b * MM + row0)) * NN;
    // stage K slice into smem (9216 float4 / 1024 thr = 9 each)
    {
        const float4* src = (const float4*)Kbase;
        float4* dst = (float4*)sk;
#pragma unroll
        for (int i = 0; i < KSLICE / 4 / 1024; ++i)
            dst[tid + 1024 * i] = src[tid + 1024 * i];
    }
    __syncthreads();
    cluster_sync();   // all mbarriers initialized before any remote arrive

    const int rl0 = wid * 2, rl1 = wid * 2 + 1;
    const float* K0 = sk + rl0 * NN;
    const float* K1 = sk + rl1 * NN;

    for (int it = 0; it < 5; ++it) {
        // ---- build v from previous partials (all reads LOCAL smem) ----
        if (tid < NN) {
            if (it == 0) {
                vsm[tid] = 1.0f;
            } else {
                const float(*vb)[NN] = vbuf[(it - 1) & 1];
                float s = vb[0][tid] + vb[1][tid] + vb[2][tid] + vb[3][tid];
                vsm[tid] = __powf(MU_C / (s + EPSF), FI_C);
            }
        }
        __syncthreads();

        // ---- phase A: u for 2 rows per warp ----
        {
            float acc0 = 0.0f, acc1 = 0.0f;
#pragma unroll
            for (int i = 0; i < 18; ++i) {
                int j = lane + 32 * i;
                float vv = vsm[j];
                acc0 += K0[j] * vv;
                acc1 += K1[j] * vv;
            }
            acc0 = warp_sum(acc0);
            acc1 = warp_sum(acc1);
            if (lane == 0) {
                usm[rl0] = __powf(nusm[rl0] / (acc0 + EPSF), FI_C);
                usm[rl1] = __powf(nusm[rl1] / (acc1 + EPSF), FI_C);
            }
        }
        __syncthreads();

        // ---- phase B: partial Ktu over 64 rows, split in row halves ----
        {
            int half = tid >> 9;          // 0 or 1
            int ct = tid & 511;
            const float* base = sk + half * 32 * NN;
            const float* uh = usm + half * 32;
            float a0 = 0.0f, a1 = 0.0f;
#pragma unroll 8
            for (int r = 0; r < 32; ++r) {
                float ur = uh[r];
                a0 += base[r * NN + ct] * ur;
                if (ct < 64) a1 += base[r * NN + 512 + ct] * ur;
            }
            pbuf[half][ct] = a0;
            if (ct < 64) pbuf2[half][ct] = a1;
        }
        __syncthreads();

        // ---- distribute combined partial to all 4 CTAs' vbuf[it&1][rank] ----
        if (tid < NN) {
            float val = (tid < 512) ? (pbuf[0][tid] + pbuf[1][tid])
                                    : (pbuf2[0][tid - 512] + pbuf2[1][tid - 512]);
            uint32_t laddr = smem_u32(&vbuf[it & 1][rank][tid]);
            vbuf[it & 1][rank][tid] = val;   // local copy
#pragma unroll
            for (int p = 0; p < 4; ++p)
                if (p != rank) dsmem_store(laddr, p, val);
        }
        __syncthreads();
        if (tid == 0) {
            asm volatile("fence.acq_rel.cluster;" ::: "memory");
#pragma unroll
            for (int p = 0; p < 4; ++p) mbar_arrive_rank(mb, p);
        }
        mbar_wait_parity(mb, (uint32_t)(it & 1));
    }

    // ---- tail: final v, then FUSED loss: ctot = sum_rows mask*(P_hat . LS) ----
    if (tid < NN) {
        const float(*vb)[NN] = vbuf[0];
        float s = vb[0][tid] + vb[1][tid] + vb[2][tid] + vb[3][tid];
        vsm[tid] = __powf(MU_C / (s + EPSF), FI_C);
    }
    __syncthreads();
    float ctot = 0.0f;
#pragma unroll
    for (int r = 0; r < 2; ++r) {
        int rl = wid * 2 + r;
        const float* Kr = sk + rl * NN;
        const float* Lg = g_LS + ((size_t)(b * MM + row0 + rl)) * NN;
        float u = usm[rl];
        float rs = 0.0f, da = 0.0f;
#pragma unroll
        for (int i = 0; i < 18; ++i) {
            int j = lane + 32 * i;
            float p = u * Kr[j] * vsm[j];
            rs += p;
            da += p * __ldcg(Lg + j);
        }
        rs = warp_sum(rs);
        da = warp_sum(da);
        if (lane == 0) ctot += masksm[rl] * da / (rs + EPSF);
    }
    // block reduce 32 warp partials (lane 0 of each warp holds value)
    if (lane == 0) red[wid] = ctot;
    __syncthreads();
    if (tid < 32) {
        float r = red[tid];
        r = warp_sum(r);
        if (tid == 0) {
            g_psum[blockIdx.x] = r;
            __threadfence();
            unsigned t = atomicAdd(&g_done, 1u);
            last = (t == 63u);
        }
    }
    __syncthreads();
    if (last) {
        if (tid == 0) g_done = 0;  // reset for next graph replay
        if (tid < 32) {
            float s = __ldcg(g_psum + tid) + __ldcg(g_psum + tid + 32);
            s = warp_sum(s);
            if (tid == 0) out[0] = -s * (1.0f / (float)(BB * HH * MM));
        }
    }
    cluster_sync();   // teardown safety
}

// ---------------- logsum: LS[b,m,j] = sum_h log(student + eps) ----------------
// Forked at capture start; overlaps prep + GEMM; joined before sinkhorn.
__global__ void __launch_bounds__(288) logsum_kernel(const float* __restrict__ student) {
    int blk = blockIdx.x, tid = threadIdx.x;
    int b = blk >> 8, m = blk & 255;
    const float* sbase = student + ((size_t)(b * HH) * MM + m) * NN;
    float2 sv[HH];
#pragma unroll
    for (int h = 0; h < HH; ++h)
        sv[h] = __ldcs((const float2*)(sbase + (size_t)h * MM * NN) + tid);
    float2 r = make_float2(0.0f, 0.0f);
#pragma unroll
    for (int h = 0; h < HH; ++h) {
        r.x += __logf(sv[h].x + EPSF);
        r.y += __logf(sv[h].y + EPSF);
    }
    ((float2*)(g_LS + (size_t)blk * NN))[tid] = r;
}

// ---------------- launch ----------------
extern "C" void kernel_launch(void* const* d_in, const int* in_sizes, int n_in,
                              void* d_out, int out_size) {
    const float *student = nullptr, *visual = nullptr, *text = nullptr, *mask = nullptr;
    for (int i = 0; i < n_in; ++i) {
        long sz = in_sizes[i];
        if (sz == (long)BB * HH * MM * NN) student = (const float*)d_in[i];
        else if (sz == (long)BB * NN * DD) visual = (const float*)d_in[i];
        else if (sz == (long)BB * MM * DD) text = (const float*)d_in[i];
        else if (sz == (long)BB * MM) mask = (const float*)d_in[i];
    }
    float* out = (float*)d_out;

    static cudaStream_t s2;
    static cudaEvent_t evA, evL;
    static bool init_done = false;
    if (!init_done) {
        cudaFuncSetAttribute(gemm_expK_kernel,
                             cudaFuncAttributeMaxDynamicSharedMemorySize,
                             3 * (ASTG + BSTG));
        cudaFuncSetAttribute(sinkhorn_kernel,
                             cudaFuncAttributeMaxDynamicSharedMemorySize,
                             KSLICE * 4);
        cudaStreamCreateWithFlags(&s2, cudaStreamNonBlocking);
        cudaEventCreateWithFlags(&evA, cudaEventDisableTiming);
        cudaEventCreateWithFlags(&evL, cudaEventDisableTiming);
        init_done = true;
    }

    // stream 0: prep -> gemm -> (join logsum) -> sinkhorn (writes out)
    // stream s2: logsum (student only), forked at start
    cudaEventRecord(evA, 0);
    cudaStreamWaitEvent(s2, evA, 0);
    logsum_kernel<<<BB * MM, 288, 0, s2>>>(student);
    cudaEventRecord(evL, s2);
    prep_kernel<<<(BB * NN + BB * MM) / 8, 256>>>(visual, text);
    gemm_expK_kernel<<<dim3(NN / 64, MM / 128, BB), 256, 3 * (ASTG + BSTG)>>>();
    cudaStreamWaitEvent(0, evL, 0);
    sinkhorn_kernel<<<64, 1024, KSLICE * 4>>>(mask, out);
}

// round 16
// speedup vs baseline: 1.1956x; 1.0651x over previous
#include <cuda_runtime.h>
#include <cuda_bf16.h>
#include <cstdint>

// Problem constants: B=16, H=16, M=256, N=576, D=1024
#define BB 16
#define HH 16
#define MM 256
#define NN 576
#define DD 1024

#define EPSF 1e-8f
#define MU_C (1.0f / 576.0f)
#define FI_C (1.0f / 1.1f)

// ---------------- device scratch ----------------
__device__ __nv_bfloat16 g_xb[BB * NN * DD];   // visual feats bf16 (raw)
__device__ __nv_bfloat16 g_yb[BB * MM * DD];   // text feats bf16 (raw)
__device__ float g_inv_nx[BB * NN];
__device__ float g_inv_ny[BB * MM];
__device__ float g_K[BB * MM * NN];            // exp(-cost/eps)
__device__ float g_LS[BB * MM * NN];           // sum_h log(student)
__device__ float g_psum[64];                   // per-sinkhorn-CTA loss partials
__device__ unsigned g_done;

// ---------------- helpers ----------------
__device__ __forceinline__ float warp_sum(float v) {
#pragma unroll
    for (int o = 16; o; o >>= 1) v += __shfl_xor_sync(0xffffffffu, v, o);
    return v;
}

__device__ __forceinline__ float block_sum1024(float v, volatile float* red) {
    int tid = threadIdx.x;
    float w = warp_sum(v);
    if ((tid & 31) == 0) red[tid >> 5] = w;
    __syncthreads();
    if (tid < 32) {
        float r = red[tid];
        r = warp_sum(r);
        if (tid == 0) red[0] = r;
    }
    __syncthreads();
    float out = red[0];
    __syncthreads();
    return out;
}

__device__ __forceinline__ void cluster_sync() {
    asm volatile("barrier.cluster.arrive.aligned;" ::: "memory");
    asm volatile("barrier.cluster.wait.aligned;" ::: "memory");
}

__device__ __forceinline__ uint32_t smem_u32(const void* p) {
    return (uint32_t)__cvta_generic_to_shared(p);
}

// store 8 bytes into the same smem offset of cluster CTA `rank`
__device__ __forceinline__ void dsmem_store64(uint32_t laddr, int rank, float2 v) {
    uint32_t r;
    unsigned long long u;
    memcpy(&u, &v, 8);
    asm volatile("mapa.shared::cluster.u32 %0, %1, %2;" : "=r"(r) : "r"(laddr), "r"(rank));
    asm volatile("st.shared::cluster.b64 [%0], %1;" :: "r"(r), "l"(u) : "memory");
}

__device__ __forceinline__ void mbar_arrive_rank(uint32_t laddr, int rank) {
    uint32_t r;
    asm volatile("mapa.shared::cluster.u32 %0, %1, %2;" : "=r"(r) : "r"(laddr), "r"(rank));
    asm volatile("mbarrier.arrive.shared::cluster.b64 _, [%0];" :: "r"(r) : "memory");
}

__device__ __forceinline__ void mbar_wait_parity(uint32_t mb, uint32_t parity) {
    uint32_t done;
    asm volatile(
        "{\n\t.reg .pred p;\n\t"
        "mbarrier.try_wait.parity.acquire.cluster.shared::cta.b64 p, [%1], %2;\n\t"
        "selp.b32 %0,1,0,p;\n\t}"
        : "=r"(done) : "r"(mb), "r"(parity) : "memory");
    while (!done) {
        asm volatile(
            "{\n\t.reg .pred p;\n\t"
            "mbarrier.try_wait.parity.acquire.cluster.shared::cta.b64 p, [%1], %2, 0x989680;\n\t"
            "selp.b32 %0,1,0,p;\n\t}"
            : "=r"(done) : "r"(mb), "r"(parity) : "memory");
    }
}

__device__ __forceinline__ void ldsm4(uint32_t* r, uint32_t addr) {
    asm volatile("ldmatrix.sync.aligned.m8n8.x4.shared.b16 {%0,%1,%2,%3}, [%4];"
                 : "=r"(r[0]), "=r"(r[1]), "=r"(r[2]), "=r"(r[3]) : "r"(addr));
}

__device__ __forceinline__ void mma16816(float* c, const uint32_t* a, const uint32_t* b) {
    asm volatile(
        "mma.sync.aligned.m16n8k16.row.col.f32.bf16.bf16.f32 "
        "{%0,%1,%2,%3}, {%4,%5,%6,%7}, {%8,%9}, {%0,%1,%2,%3};"
        : "+f"(c[0]), "+f"(c[1]), "+f"(c[2]), "+f"(c[3])
        : "r"(a[0]), "r"(a[1]), "r"(a[2]), "r"(a[3]), "r"(b[0]), "r"(b[1]));
}

__device__ __forceinline__ void cp16(uint32_t dst, const void* src) {
    asm volatile("cp.async.cg.shared.global [%0], [%1], 16;" :: "r"(dst), "l"(src));
}

// ---------------- kernel 1: norms + bf16 conversion ----------------
__global__ void __launch_bounds__(256) prep_kernel(const float* __restrict__ visual,
                                                   const float* __restrict__ text) {
    int warp = blockIdx.x * 8 + (threadIdx.x >> 5);
    int lane = threadIdx.x & 31;
    const int VROWS = BB * NN;
    const float* src;
    __nv_bfloat16* dst;
    float* invp;
    if (warp < VROWS) {
        src = visual + (size_t)warp * DD;
        dst = g_xb + (size_t)warp * DD;
        invp = g_inv_nx + warp;
    } else {
        int r = warp - VROWS;
        src = text + (size_t)r * DD;
        dst = g_yb + (size_t)r * DD;
        invp = g_inv_ny + r;
    }
    const float4* s4 = (const float4*)src;
    uint2* d2 = (uint2*)dst;
    float ss = 0.0f;
#pragma unroll
    for (int i = 0; i < 8; ++i) {
        float4 v = __ldcs(&s4[lane + 32 * i]);
        ss += v.x * v.x + v.y * v.y + v.z * v.z + v.w * v.w;
        uint32_t lo = (uint32_t)__bfloat16_as_ushort(__float2bfloat16_rn(v.x))
                    | ((uint32_t)__bfloat16_as_ushort(__float2bfloat16_rn(v.y)) << 16);
        uint32_t hi = (uint32_t)__bfloat16_as_ushort(__float2bfloat16_rn(v.z))
                    | ((uint32_t)__bfloat16_as_ushort(__float2bfloat16_rn(v.w)) << 16);
        d2[lane + 32 * i] = make_uint2(lo, hi);
    }
    ss = warp_sum(ss);
    if (lane == 0) *invp = rsqrtf(ss + 1e-12f);
}

// ---------------- kernel 2: HMMA bf16 GEMM, 3-stage cp.async pipeline --------
#define ASTG 16384
#define BSTG 8192
__global__ void __launch_bounds__(256) gemm_expK_kernel() {
    extern __shared__ __align__(16) char dsm[];
    uint32_t SBASE = (uint32_t)__cvta_generic_to_shared(dsm);
    uint32_t SA = SBASE;                 // 3 x 16384
    uint32_t SB = SBASE + 3 * ASTG;      // 3 x 8192

    int tid = threadIdx.x, wid = tid >> 5, lane = tid & 31;
    int nt = blockIdx.x, mt = blockIdx.y, b = blockIdx.z;
    int wm = wid & 3, wn = wid >> 2;

    const __nv_bfloat16* Abase = g_yb + ((size_t)(b * MM + mt * 128)) * DD;
    const __nv_bfloat16* Bbase = g_xb + ((size_t)(b * NN + nt * 64)) * DD;

    float acc[2][4][4];
#pragma unroll
    for (int i = 0; i < 2; ++i)
#pragma unroll
        for (int j = 0; j < 4; ++j)
#pragma unroll
            for (int k = 0; k < 4; ++k) acc[i][j][k] = 0.0f;

    int a_row0 = wm * 32 + ((lane >> 3) & 1) * 8 + (lane & 7);
    int a_chunk_sel = (lane >> 4);
    int b_row0 = wn * 32 + (lane >> 4) * 8 + (lane & 7);
    int b_chunk_sel = ((lane >> 3) & 1);

    int arow[4], acol[4], brow[2], bcol[2];
    uint32_t aoff[4], boff[2];
#pragma unroll
    for (int q = 0; q < 4; ++q) {
        int c = tid + 256 * q;
        arow[q] = c >> 3; acol[q] = c & 7;
        aoff[q] = arow[q] * 128 + ((acol[q] ^ (arow[q] & 7)) * 16);
    }
#pragma unroll
    for (int q = 0; q < 2; ++q) {
        int c = tid + 256 * q;
        brow[q] = c >> 3; bcol[q] = c & 7;
        boff[q] = brow[q] * 128 + ((bcol[q] ^ (brow[q] & 7)) * 16);
    }

#define ISSUE(s)                                                               \
    do {                                                                       \
        int st_ = (s) % 3;                                                     \
        int kb_ = (s) * 64;                                                    \
        uint32_t ab_ = SA + st_ * ASTG, bb_ = SB + st_ * BSTG;                 \
        _Pragma("unroll")                                                      \
        for (int q = 0; q < 4; ++q)                                            \
            cp16(ab_ + aoff[q], Abase + (size_t)arow[q] * DD + kb_ + acol[q] * 8); \
        _Pragma("unroll")                                                      \
        for (int q = 0; q < 2; ++q)                                            \
            cp16(bb_ + boff[q], Bbase + (size_t)brow[q] * DD + kb_ + bcol[q] * 8); \
        asm volatile("cp.async.commit_group;" ::: "memory");                   \
    } while (0)

    ISSUE(0);
    ISSUE(1);

    for (int s = 0; s < 16; ++s) {
        if (s == 15)
            asm volatile("cp.async.wait_group 0;" ::: "memory");
        else
            asm volatile("cp.async.wait_group 1;" ::: "memory");
        __syncthreads();
        if (s + 2 < 16) ISSUE(s + 2);

        uint32_t SAc = SA + (s % 3) * ASTG;
        uint32_t SBc = SB + (s % 3) * BSTG;
#pragma unroll
        for (int kk = 0; kk < 4; ++kk) {
            uint32_t a0[4], a1[4], bA[4], bB[4];
            {
                int row = a_row0;
                int ch = kk * 2 + a_chunk_sel;
                ldsm4(a0, SAc + row * 128 + ((ch ^ (row & 7)) * 16));
                row = a_row0 + 16;
                ldsm4(a1, SAc + row * 128 + ((ch ^ (row & 7)) * 16));
            }
            {
                int row = b_row0;
                int ch = kk * 2 + b_chunk_sel;
                ldsm4(bA, SBc + row * 128 + ((ch ^ (row & 7)) * 16));
                row = b_row0 + 16;
                ldsm4(bB, SBc + row * 128 + ((ch ^ (row & 7)) * 16));
            }
            mma16816(acc[0][0], a0, bA + 0);
            mma16816(acc[0][1], a0, bA + 2);
            mma16816(acc[0][2], a0, bB + 0);
            mma16816(acc[0][3], a0, bB + 2);
            mma16816(acc[1][0], a1, bA + 0);
            mma16816(acc[1][1], a1, bA + 2);
            mma16816(acc[1][2], a1, bB + 0);
            mma16816(acc[1][3], a1, bB + 2);
        }
    }

    // epilogue: scale by inv-norms, exp((cos-1)*10), write g_K
    int mrow_base = mt * 128 + wm * 32 + (lane >> 2);
    int ncol_base = nt * 64 + wn * 32 + (lane & 3) * 2;
    const float* invx = g_inv_nx + b * NN;
    const float* invy = g_inv_ny + b * MM;
#pragma unroll
    for (int mi = 0; mi < 2; ++mi) {
#pragma unroll
        for (int half = 0; half < 2; ++half) {
            int m = mrow_base + mi * 16 + half * 8;
            float invm = invy[m];
            float* out = g_K + ((size_t)(b * MM + m)) * NN;
#pragma unroll
            for (int ni = 0; ni < 4; ++ni) {
                int n = ncol_base + ni * 8;
                float c0 = acc[mi][ni][half * 2 + 0];
                float c1 = acc[mi][ni][half * 2 + 1];
                float s0 = c0 * invm * invx[n];
                float s1 = c1 * invm * invx[n + 1];
                float2 e;
                e.x = __expf((s0 - 1.0f) * 10.0f);
                e.y = __expf((s1 - 1.0f) * 10.0f);
                *(float2*)(out + n) = e;
            }
        }
    }
}

// ---------------- kernel 3: Sinkhorn (bf16 K in smem) + FUSED loss tail -------
// grid = 64 CTAs (16 clusters x 4) x 1024 threads. CTA owns 64 K-rows as bf16
// (72 KB smem). Per iteration: phase A, phase B, reduce-scatter of Ktu partials
// (each rank owns 144 columns -> powf only 144/CTA, was 576), broadcast of v.
// Two mbarriers per iteration, no cluster barrier in the loop.
#define SK_BYTES (64 * NN * 2)
__global__ void __cluster_dims__(4, 1, 1) __launch_bounds__(1024)
sinkhorn_kernel(const float* __restrict__ mask, float* __restrict__ out) {
    extern __shared__ __align__(16) __nv_bfloat16 sk[];   // [64][576] bf16
    __shared__ float2 vsm2[288];                          // v as pairs
    __shared__ float usm[64];
    __shared__ float masksm[64];
    __shared__ float nusm[64];
    __shared__ float red[32];
    __shared__ float2 pbuf[2][288];                       // rowgroup partials
    __shared__ float2 rsbuf[4][72];                       // reduce-scatter in
    __shared__ __align__(8) unsigned long long mbar1, mbar2;
    __shared__ bool last;

    int tid = threadIdx.x;
    int b = blockIdx.x >> 2;
    int rank = blockIdx.x & 3;
    int wid = tid >> 5, lane = tid & 31;
    const int row0 = rank * 64;
    uint32_t mb1 = smem_u32(&mbar1);
    uint32_t mb2 = smem_u32(&mbar2);

    if (tid == 0) {
        asm volatile("mbarrier.init.shared.b64 [%0], %1;" :: "r"(mb1), "r"(4u) : "memory");
        asm volatile("mbarrier.init.shared.b64 [%0], %1;" :: "r"(mb2), "r"(4u) : "memory");
    }

    float mv = (tid < MM) ? mask[b * MM + tid] : 0.0f;
    float msum = block_sum1024(mv, red);
    if (tid < 64) {
        float mk = mask[b * MM + row0 + tid];
        masksm[tid] = mk;
        nusm[tid] = mk / (msum + EPSF);
    }

    const float* Kbase = g_K + ((size_t)(b * MM + row0)) * NN;
    // stage K slice into smem as bf16 (9216 float4 reads / 1024 thr = 9 each)
    {
        const float4* src = (const float4*)Kbase;
        uint2* dst = (uint2*)sk;
#pragma unroll
        for (int i = 0; i < 9; ++i) {
            float4 v = src[tid + 1024 * i];
            uint32_t lo = (uint32_t)__bfloat16_as_ushort(__float2bfloat16_rn(v.x))
                        | ((uint32_t)__bfloat16_as_ushort(__float2bfloat16_rn(v.y)) << 16);
            uint32_t hi = (uint32_t)__bfloat16_as_ushort(__float2bfloat16_rn(v.z))
                        | ((uint32_t)__bfloat16_as_ushort(__float2bfloat16_rn(v.w)) << 16);
            dst[tid + 1024 * i] = make_uint2(lo, hi);
        }
    }
    if (tid < 288) vsm2[tid] = make_float2(1.0f, 1.0f);
    __syncthreads();
    cluster_sync();   // mbarriers initialized cluster-wide before remote ops

    const int rl0 = wid * 2, rl1 = wid * 2 + 1;
    const __nv_bfloat162* K0p = (const __nv_bfloat162*)sk + (size_t)rl0 * 288;
    const __nv_bfloat162* K1p = (const __nv_bfloat162*)sk + (size_t)rl1 * 288;

    for (int it = 0; it < 5; ++it) {
        // ---- phase A: u for 2 rows per warp (bf16 pairs) ----
        {
            float acc0 = 0.0f, acc1 = 0.0f;
#pragma unroll
            for (int i = 0; i < 9; ++i) {
                int j2 = lane + 32 * i;
                float2 vv = vsm2[j2];
                float2 k0 = __bfloat1622float2(K0p[j2]);
                float2 k1 = __bfloat1622float2(K1p[j2]);
                acc0 += k0.x * vv.x + k0.y * vv.y;
                acc1 += k1.x * vv.x + k1.y * vv.y;
            }
            acc0 = warp_sum(acc0);
            acc1 = warp_sum(acc1);
            if (lane == 0) {
                usm[rl0] = __powf(nusm[rl0] / (acc0 + EPSF), FI_C);
                usm[rl1] = __powf(nusm[rl1] / (acc1 + EPSF), FI_C);
            }
        }
        __syncthreads();

        // ---- phase B: partial Ktu, 576 threads = 288 pairs x 2 row groups ----
        if (tid < 576) {
            int rowgroup = tid >= 288;
            int g = tid - rowgroup * 288;
            const __nv_bfloat162* basep =
                (const __nv_bfloat162*)sk + (size_t)rowgroup * 32 * 288 + g;
            const float* uh = usm + rowgroup * 32;
            float ax = 0.0f, ay = 0.0f;
#pragma unroll 8
            for (int r = 0; r < 32; ++r) {
                float ur = uh[r];
                float2 k = __bfloat1622float2(basep[(size_t)r * 288]);
                ax += k.x * ur;
                ay += k.y * ur;
            }
            pbuf[rowgroup][g] = make_float2(ax, ay);
        }
        __syncthreads();

        // ---- reduce-scatter: push my partial for pair g to its owner rank ----
        if (tid < 288) {
            float2 p0 = pbuf[0][tid], p1 = pbuf[1][tid];
            float2 val = make_float2(p0.x + p1.x, p0.y + p1.y);
            int owner = tid / 72;
            int slot = tid - owner * 72;
            if (owner == rank) {
                rsbuf[rank][slot] = val;
            } else {
                dsmem_store64(smem_u32(&rsbuf[rank][slot]), owner, val);
            }
        }
        __syncthreads();
        if (tid == 0) {
            asm volatile("fence.acq_rel.cluster;" ::: "memory");
#pragma unroll
            for (int p = 0; p < 4; ++p) mbar_arrive_rank(mb1, p);
        }
        mbar_wait_parity(mb1, (uint32_t)(it & 1));

        // ---- own 72 pairs: sum 4 rank partials, powf, broadcast v ----
        if (tid < 72) {
            float2 s0 = rsbuf[0][tid], s1 = rsbuf[1][tid];
            float2 s2 = rsbuf[2][tid], s3 = rsbuf[3][tid];
            float sx = s0.x + s1.x + s2.x + s3.x;
            float sy = s0.y + s1.y + s2.y + s3.y;
            float2 v;
            v.x = __powf(MU_C / (sx + EPSF), FI_C);
            v.y = __powf(MU_C / (sy + EPSF), FI_C);
            int gp = rank * 72 + tid;
            vsm2[gp] = v;
            uint32_t laddr = smem_u32(&vsm2[gp]);
#pragma unroll
            for (int p = 0; p < 4; ++p)
                if (p != rank) dsmem_store64(laddr, p, v);
        }
        __syncthreads();
        if (tid == 0) {
            asm volatile("fence.acq_rel.cluster;" ::: "memory");
#pragma unroll
            for (int p = 0; p < 4; ++p) mbar_arrive_rank(mb2, p);
        }
        mbar_wait_parity(mb2, (uint32_t)(it & 1));
    }

    // ---- tail: FUSED loss ctot = sum_rows mask*(P_hat . LS) ----
    float ctot = 0.0f;
#pragma unroll
    for (int r = 0; r < 2; ++r) {
        int rl = wid * 2 + r;
        const __nv_bfloat162* Kp = (const __nv_bfloat162*)sk + (size_t)rl * 288;
        const float2* Lg2 = (const float2*)(g_LS + ((size_t)(b * MM + row0 + rl)) * NN);
        float u = usm[rl];
        float rs = 0.0f, da = 0.0f;
#pragma unroll
        for (int i = 0; i < 9; ++i) {
            int j2 = lane + 32 * i;
            float2 k = __bfloat1622float2(Kp[j2]);
            float2 vv = vsm2[j2];
            float2 l = __ldcg(Lg2 + j2);
            float px = u * k.x * vv.x;
            float py = u * k.y * vv.y;
            rs += px + py;
            da += px * l.x + py * l.y;
        }
        rs = warp_sum(rs);
        da = warp_sum(da);
        if (lane == 0) ctot += masksm[rl] * da / (rs + EPSF);
    }
    if (lane == 0) red[wid] = ctot;
    __syncthreads();
    if (tid < 32) {
        float r = red[tid];
        r = warp_sum(r);
        if (tid == 0) {
            g_psum[blockIdx.x] = r;
            __threadfence();
            unsigned t = atomicAdd(&g_done, 1u);
            last = (t == 63u);
        }
    }
    __syncthreads();
    if (last) {
        if (tid == 0) g_done = 0;  // reset for next graph replay
        if (tid < 32) {
            float s = __ldcg(g_psum + tid) + __ldcg(g_psum + tid + 32);
            s = warp_sum(s);
            if (tid == 0) out[0] = -s * (1.0f / (float)(BB * HH * MM));
        }
    }
    cluster_sync();   // teardown safety
}

// ---------------- logsum: LS[b,m,j] = sum_h log(student + eps) ----------------
// Forked at capture start; overlaps prep + GEMM; joined before sinkhorn.
__global__ void __launch_bounds__(288) logsum_kernel(const float* __restrict__ student) {
    int blk = blockIdx.x, tid = threadIdx.x;
    int b = blk >> 8, m = blk & 255;
    const float* sbase = student + ((size_t)(b * HH) * MM + m) * NN;
    float2 sv[HH];
#pragma unroll
    for (int h = 0; h < HH; ++h)
        sv[h] = __ldcs((const float2*)(sbase + (size_t)h * MM * NN) + tid);
    float2 r = make_float2(0.0f, 0.0f);
#pragma unroll
    for (int h = 0; h < HH; ++h) {
        r.x += __logf(sv[h].x + EPSF);
        r.y += __logf(sv[h].y + EPSF);
    }
    ((float2*)(g_LS + (size_t)blk * NN))[tid] = r;
}

// ---------------- launch ----------------
extern "C" void kernel_launch(void* const* d_in, const int* in_sizes, int n_in,
                              void* d_out, int out_size) {
    const float *student = nullptr, *visual = nullptr, *text = nullptr, *mask = nullptr;
    for (int i = 0; i < n_in; ++i) {
        long sz = in_sizes[i];
        if (sz == (long)BB * HH * MM * NN) student = (const float*)d_in[i];
        else if (sz == (long)BB * NN * DD) visual = (const float*)d_in[i];
        else if (sz == (long)BB * MM * DD) text = (const float*)d_in[i];
        else if (sz == (long)BB * MM) mask = (const float*)d_in[i];
    }
    float* out = (float*)d_out;

    static cudaStream_t s2;
    static cudaEvent_t evA, evL;
    static bool init_done = false;
    if (!init_done) {
        cudaFuncSetAttribute(gemm_expK_kernel,
                             cudaFuncAttributeMaxDynamicSharedMemorySize,
                             3 * (ASTG + BSTG));
        cudaFuncSetAttribute(sinkhorn_kernel,
                             cudaFuncAttributeMaxDynamicSharedMemorySize,
                             SK_BYTES);
        cudaStreamCreateWithFlags(&s2, cudaStreamNonBlocking);
        cudaEventCreateWithFlags(&evA, cudaEventDisableTiming);
        cudaEventCreateWithFlags(&evL, cudaEventDisableTiming);
        init_done = true;
    }

    // stream 0: prep -> gemm -> (join logsum) -> sinkhorn (writes out)
    // stream s2: logsum (student only), forked at start
    cudaEventRecord(evA, 0);
    cudaStreamWaitEvent(s2, evA, 0);
    logsum_kernel<<<BB * MM, 288, 0, s2>>>(student);
    cudaEventRecord(evL, s2);
    prep_kernel<<<(BB * NN + BB * MM) / 8, 256>>>(visual, text);
    gemm_expK_kernel<<<dim3(NN / 64, MM / 128, BB), 256, 3 * (ASTG + BSTG)>>>();
    cudaStreamWaitEvent(0, evL, 0);
    sinkhorn_kernel<<<64, 1024, SK_BYTES>>>(mask, out);
}